// round 8
// baseline (speedup 1.0000x reference)
#include <cuda_runtime.h>
#include <stdint.h>

#define COLA 528                 // A row stride (bytes)
#define COLB 544                 // B col stride (bytes)
#define ASZ (128 * COLA)         // 67584
#define BSZ (64 * COLB)          // 34816
#define W16SZ (256 * 64 * 4)     // 65536: [kpair][col] u32 (s16 pair per word)

static __device__ __align__(16) signed char g_Wd1[BSZ];
static __device__ __align__(16) signed char g_Wd2[BSZ];
static __device__ __align__(16) uint32_t    g_W16[256 * 64];
static __device__ float g_corr[64];
static __device__ float g_sc;         // (2/255) * s1 / 128
static __device__ int   g_stride;     // u32 words per x element (1=int32, 2=int64)

// ---------------------------------------------------------------------------
__device__ __forceinline__ void imma(int* c, uint32_t a0, uint32_t a1,
                                     uint32_t a2, uint32_t a3,
                                     uint32_t b0, uint32_t b1) {
    asm volatile(
        "mma.sync.aligned.m16n8k32.row.col.s32.s8.s8.s32 "
        "{%0,%1,%2,%3}, {%4,%5,%6,%7}, {%8,%9}, {%0,%1,%2,%3};"
        : "+r"(c[0]), "+r"(c[1]), "+r"(c[2]), "+r"(c[3])
        : "r"(a0), "r"(a1), "r"(a2), "r"(a3), "r"(b0), "r"(b1));
}

// ---------------------------------------------------------------------------
// Prep: grid 64 (block = col o), 512 thr (thread = k). Redundant per-block
// max reduction; two s8 digits (radix 128) in MMA fragment order; packed s16
// weights for the dp2a path; column sums.
// ---------------------------------------------------------------------------
static __global__ void bf_prep(const float* __restrict__ W,
                               const uint32_t* __restrict__ xw)
{
    __shared__ float red[512];
    int o = blockIdx.x, k = threadIdx.x;

    if (o == 0 && k == 0) {
        uint32_t acc = 0;
        for (int j = 1; j < 256; j += 2) acc |= xw[j];
        g_stride = (acc == 0u) ? 2 : 1;
    }

    float mx = 0.f;
    for (int i = k; i < 496 * 64; i += 512) mx = fmaxf(mx, fabsf(W[i]));
    red[k] = mx;
    __syncthreads();
    for (int d = 256; d; d >>= 1) {
        if (k < d) red[k] = fmaxf(red[k], red[k + d]);
        __syncthreads();
    }
    float maxabs = fmaxf(red[0], 1e-30f);
    __syncthreads();

    float s1 = maxabs * (1.0f / 127.0f), inv1 = 127.0f / maxabs;
    float inv2 = 128.0f / s1;

    float w = (k < 496) ? W[k * 64 + o] : 0.f;
    int d1 = __float2int_rn(w * inv1);
    d1 = max(-127, min(127, d1));
    float r = w - s1 * (float)d1;
    int d2 = __float2int_rn(r * inv2);
    d2 = max(-127, min(127, d2));

    int ks = k >> 5, wrd = (k >> 2) & 7, tig = wrd & 3, half = wrd >> 2, byt = k & 3;
    int addr = o * COLB + ks * 32 + tig * 8 + half * 4 + byt;
    g_Wd1[addr] = (signed char)d1;
    g_Wd2[addr] = (signed char)d2;

    // packed s16 weight: w16 = 128*d1 + d2, layout [kpair][col]
    int w16 = (d1 << 7) + d2;
    ((short*)g_W16)[((k >> 1) * 64 + o) * 2 + (k & 1)] = (short)w16;

    red[k] = w;
    __syncthreads();
    for (int d = 256; d; d >>= 1) {
        if (k < d) red[k] += red[k + d];
        __syncthreads();
    }
    if (k == 0) {
        g_corr[o] = red[0] * (1.0f / 255.0f);
        if (o == 0) g_sc = (2.0f / 255.0f) * s1 * (1.0f / 128.0f);
    }
}

// ---------------------------------------------------------------------------
// Main persistent kernel. SMEM: sA | B1 | B2 | W16 | bw(136w) | corr
// ---------------------------------------------------------------------------
#define SA_OFF   0
#define SB1_OFF  (ASZ)
#define SB2_OFF  (ASZ + BSZ)
#define SW_OFF   (ASZ + 2 * BSZ)
#define BW_OFF   (ASZ + 2 * BSZ + W16SZ)
#define CORR_OFF (BW_OFF + 544)
#define SMEM_DYN (CORR_OFF + 256)       // 203552

static __global__ void __launch_bounds__(512, 1)
bf_main(const uint32_t* __restrict__ xw, float* __restrict__ out)
{
    extern __shared__ __align__(16) char sm[];
    char*      sA    = sm + SA_OFF;
    char*      sB1   = sm + SB1_OFF;
    char*      sB2   = sm + SB2_OFF;
    uint32_t*  sW    = (uint32_t*)(sm + SW_OFF);
    uint32_t*  bw    = (uint32_t*)(sm + BW_OFF);
    float*     scorr = (float*)(sm + CORR_OFF);

    int t = threadIdx.x, lane = t & 31, wid = t >> 5;
    const int stride = g_stride;
    const float sc = g_sc;

    // ---- invariants: A build (thread -> row t>>2, quarter t&3) ----
    const int r = t >> 2, q = t & 3;
    const int g = r >> 3, s = r & 7;
    const int g4 = g >> 2, gr = g & 3;
    const uint32_t sel0 = 0x3210u + 0x1111u * (uint32_t)gr;
    const uint32_t sel1 = sel0 + 0x1111u;
    const uint32_t M1 = 0x01010101u * ((0xFFu << s) & 0xFFu);
    const uint32_t M2 = 0x01010101u * (0xFFu >> (8 - s));
    char* rowp = sA + r * COLA + q * 128;

    const int n0 = blockIdx.x;

    // ---- prologue: one-time copies + first bytes ----
    {
        unsigned char* bb = (unsigned char*)bw;
        bb[t] = (unsigned char)xw[((size_t)n0 * 512 + t) * (size_t)stride];
        const uint4* w1 = (const uint4*)g_Wd1;
        const uint4* w2 = (const uint4*)g_Wd2;
        const uint4* w3 = (const uint4*)g_W16;
        uint4* p1 = (uint4*)sB1;
        uint4* p2 = (uint4*)sB2;
        uint4* p3 = (uint4*)(sm + SW_OFF);
        for (int i = t; i < BSZ / 16; i += 512) { p1[i] = w1[i]; p2[i] = w2[i]; }
        for (int i = t; i < W16SZ / 16; i += 512) p3[i] = w3[i];
        if (t < 64) scorr[t] = g_corr[t];
        if (t < 8)  bw[128 + t] = 0u;
    }
    uint32_t breg = xw[((size_t)(n0 + 148) * 512 + t) * (size_t)stride];
    __syncthreads();

    if (wid < 8) {
        // ================= TENSOR WARPS: rows 0-63 =================
        const int mb = wid >> 1, nh = wid & 1;
        const int rb = mb * 16;
        const int gid = lane >> 2, tig = lane & 3;
        const int aOff = (rb + gid) * COLA + 4 * tig;
        const int colbase = nh * 32;
        const int bCol = (colbase + gid) * COLB + tig * 8;
        const int row0 = rb + gid;
        float corr0[4], corr1[4];
        #pragma unroll
        for (int nt = 0; nt < 4; nt++) {
            int col = colbase + nt * 8 + 2 * tig;
            corr0[nt] = scorr[col];
            corr1[nt] = scorr[col + 1];
        }

        for (int n = n0; n < 2048; n += 148) {
            buildA_inline:
            {
                #pragma unroll
                for (int m = 0; m < 8; m++) {
                    int wbase = q * 32 + m * 4;
                    uint32_t A0 = bw[wbase + g4];
                    uint32_t acc[4];
                    #pragma unroll
                    for (int j = 0; j < 4; j++) {
                        uint32_t B0 = bw[wbase + g4 + j + 1];
                        uint32_t X = __byte_perm(A0, B0, sel0);
                        uint32_t Y = __byte_perm(A0, B0, sel1);
                        acc[j] = (((X << s) & M1) | ((Y >> (8 - s)) & M2)) ^ 0x80808080u;
                        A0 = B0;
                    }
                    *(uint4*)(rowp + m * 16) = make_uint4(acc[0], acc[1], acc[2], acc[3]);
                }
            }
            __syncthreads();
            ((unsigned char*)bw)[t] = (unsigned char)breg;
            {
                int nb = n + 296; if (nb > 2047) nb = 2047;
                breg = xw[((size_t)nb * 512 + t) * (size_t)stride];
            }

            int c1[16], c2[16];
            #pragma unroll
            for (int i = 0; i < 16; i++) { c1[i] = 0; c2[i] = 0; }
            const char* aR = sA + aOff;
            #pragma unroll
            for (int ks = 0; ks < 16; ks++) {
                int k0 = ks * 32;
                uint32_t a0 = *(const uint32_t*)(aR + k0);
                uint32_t a2 = *(const uint32_t*)(aR + k0 + 16);
                uint32_t a1 = *(const uint32_t*)(aR + 8 * COLA + k0);
                uint32_t a3 = *(const uint32_t*)(aR + 8 * COLA + k0 + 16);
                #pragma unroll
                for (int nt = 0; nt < 4; nt++) {
                    uint2 b = *(const uint2*)(sB1 + bCol + nt * (8 * COLB) + k0);
                    imma(c1 + 4 * nt, a0, a1, a2, a3, b.x, b.y);
                    uint2 e = *(const uint2*)(sB2 + bCol + nt * (8 * COLB) + k0);
                    imma(c2 + 4 * nt, a0, a1, a2, a3, e.x, e.y);
                }
            }
            {
                float* po = out + (size_t)n * 8192;
                #pragma unroll
                for (int nt = 0; nt < 4; nt++) {
                    int col = colbase + nt * 8 + 2 * tig;
                    float2 v0, v1;
                    v0.x = fmaf(sc, (float)((c1[4*nt+0] << 7) + c2[4*nt+0]), corr0[nt]);
                    v0.y = fmaf(sc, (float)((c1[4*nt+1] << 7) + c2[4*nt+1]), corr1[nt]);
                    v1.x = fmaf(sc, (float)((c1[4*nt+2] << 7) + c2[4*nt+2]), corr0[nt]);
                    v1.y = fmaf(sc, (float)((c1[4*nt+3] << 7) + c2[4*nt+3]), corr1[nt]);
                    __stcs((float2*)(po + row0 * 64 + col), v0);
                    __stcs((float2*)(po + (row0 + 8) * 64 + col), v1);
                }
            }
            __syncthreads();
        }
    } else {
        // ================= DP2A WARPS: rows 64-127 =================
        const int r0 = 64 + (wid - 8) * 8;
        const int rp = lane >> 3, cg = lane & 7;
        const int rowA = r0 + 2 * rp;
        const char* aP0 = sA + rowA * COLA;
        const char* aP1 = aP0 + COLA;
        float corrv[8];
        #pragma unroll
        for (int i = 0; i < 8; i++) corrv[i] = scorr[cg * 8 + i];

        for (int n = n0; n < 2048; n += 148) {
            {
                #pragma unroll
                for (int m = 0; m < 8; m++) {
                    int wbase = q * 32 + m * 4;
                    uint32_t A0 = bw[wbase + g4];
                    uint32_t acc[4];
                    #pragma unroll
                    for (int j = 0; j < 4; j++) {
                        uint32_t B0 = bw[wbase + g4 + j + 1];
                        uint32_t X = __byte_perm(A0, B0, sel0);
                        uint32_t Y = __byte_perm(A0, B0, sel1);
                        acc[j] = (((X << s) & M1) | ((Y >> (8 - s)) & M2)) ^ 0x80808080u;
                        A0 = B0;
                    }
                    *(uint4*)(rowp + m * 16) = make_uint4(acc[0], acc[1], acc[2], acc[3]);
                }
            }
            __syncthreads();
            ((unsigned char*)bw)[t] = (unsigned char)breg;
            {
                int nb = n + 296; if (nb > 2047) nb = 2047;
                breg = xw[((size_t)nb * 512 + t) * (size_t)stride];
            }

            int acc[16];
            #pragma unroll
            for (int i = 0; i < 16; i++) acc[i] = 0;

            #pragma unroll 4
            for (int kb = 0; kb < 32; kb++) {
                int k0 = kb * 16;
                uint4 a0 = *(const uint4*)(aP0 + k0);
                uint4 a1 = *(const uint4*)(aP1 + k0);
                const uint32_t* aw0 = (const uint32_t*)&a0;
                const uint32_t* aw1 = (const uint32_t*)&a1;
                #pragma unroll
                for (int j = 0; j < 8; j++) {
                    const uint32_t* wp = sW + (kb * 8 + j) * 64 + cg * 8;
                    uint4 wlo = *(const uint4*)(wp);
                    uint4 whi = *(const uint4*)(wp + 4);
                    uint32_t b0 = aw0[j >> 1], b1 = aw1[j >> 1];
                    const uint32_t* wv = (const uint32_t*)&wlo;
                    const uint32_t* wv2 = (const uint32_t*)&whi;
                    if ((j & 1) == 0) {
                        #pragma unroll
                        for (int cc = 0; cc < 4; cc++) {
                            acc[cc]     = __dp2a_lo((int)wv[cc],  (int)b0, acc[cc]);
                            acc[4 + cc] = __dp2a_lo((int)wv2[cc], (int)b0, acc[4 + cc]);
                            acc[8 + cc] = __dp2a_lo((int)wv[cc],  (int)b1, acc[8 + cc]);
                            acc[12 + cc]= __dp2a_lo((int)wv2[cc], (int)b1, acc[12 + cc]);
                        }
                    } else {
                        #pragma unroll
                        for (int cc = 0; cc < 4; cc++) {
                            acc[cc]     = __dp2a_hi((int)wv[cc],  (int)b0, acc[cc]);
                            acc[4 + cc] = __dp2a_hi((int)wv2[cc], (int)b0, acc[4 + cc]);
                            acc[8 + cc] = __dp2a_hi((int)wv[cc],  (int)b1, acc[8 + cc]);
                            acc[12 + cc]= __dp2a_hi((int)wv2[cc], (int)b1, acc[12 + cc]);
                        }
                    }
                }
            }

            {
                float* po = out + (size_t)n * 8192 + cg * 8;
                float4 v;
                v.x = fmaf(sc, (float)acc[0], corrv[0]);
                v.y = fmaf(sc, (float)acc[1], corrv[1]);
                v.z = fmaf(sc, (float)acc[2], corrv[2]);
                v.w = fmaf(sc, (float)acc[3], corrv[3]);
                __stcs((float4*)(po + rowA * 64), v);
                v.x = fmaf(sc, (float)acc[4], corrv[4]);
                v.y = fmaf(sc, (float)acc[5], corrv[5]);
                v.z = fmaf(sc, (float)acc[6], corrv[6]);
                v.w = fmaf(sc, (float)acc[7], corrv[7]);
                __stcs((float4*)(po + rowA * 64 + 4), v);
                v.x = fmaf(sc, (float)acc[8], corrv[0]);
                v.y = fmaf(sc, (float)acc[9], corrv[1]);
                v.z = fmaf(sc, (float)acc[10], corrv[2]);
                v.w = fmaf(sc, (float)acc[11], corrv[3]);
                __stcs((float4*)(po + (rowA + 1) * 64), v);
                v.x = fmaf(sc, (float)acc[12], corrv[4]);
                v.y = fmaf(sc, (float)acc[13], corrv[5]);
                v.z = fmaf(sc, (float)acc[14], corrv[6]);
                v.w = fmaf(sc, (float)acc[15], corrv[7]);
                __stcs((float4*)(po + (rowA + 1) * 64 + 4), v);
            }
            __syncthreads();
        }
    }
}

// ---------------------------------------------------------------------------
extern "C" void kernel_launch(void* const* d_in, const int* in_sizes, int n_in,
                              void* d_out, int out_size)
{
    const uint32_t* xw  = (const uint32_t*)d_in[0];
    const float*    W   = (const float*)d_in[1];
    float*          out = (float*)d_out;

    cudaFuncSetAttribute(bf_main, cudaFuncAttributeMaxDynamicSharedMemorySize, SMEM_DYN);
    bf_prep<<<64, 512>>>(W, xw);
    bf_main<<<148, 512, SMEM_DYN>>>(xw, out);
}

// round 11
// speedup vs baseline: 1.1351x; 1.1351x over previous
#include <cuda_runtime.h>
#include <stdint.h>

#define COLA 528                  // A row stride (bytes)
#define COLB 544                  // B col stride (bytes)
#define ASZ   (64 * COLA)         // 33792 (M-tile = 64 rows)
#define BSZ   (64 * COLB)         // 34816 per digit

// SMEM layout (per CTA)
#define SB1_OFF  (ASZ)                    // 33792
#define SB2_OFF  (ASZ + BSZ)              // 68608
#define BW0_OFF  (ASZ + 2 * BSZ)          // 103424 (136 u32 + pad)
#define BW1_OFF  (BW0_OFF + 544)          // 103968
#define CORR_OFF (BW1_OFF + 544)          // 104512 (64 f32)
#define RED_OFF  (CORR_OFF + 256)         // 104768 (256 f32)
#define SMEM_DYN (RED_OFF + 1024)         // 105792 -> 2 CTAs/SM fit (211.6 KB)

// ---------------------------------------------------------------------------
__device__ __forceinline__ void imma(int* c, uint32_t a0, uint32_t a1,
                                     uint32_t a2, uint32_t a3,
                                     uint32_t b0, uint32_t b1) {
    asm volatile(
        "mma.sync.aligned.m16n8k32.row.col.s32.s8.s8.s32 "
        "{%0,%1,%2,%3}, {%4,%5,%6,%7}, {%8,%9}, {%0,%1,%2,%3};"
        : "+r"(c[0]), "+r"(c[1]), "+r"(c[2]), "+r"(c[3])
        : "r"(a0), "r"(a1), "r"(a2), "r"(a3), "r"(b0), "r"(b1));
}

// ---------------------------------------------------------------------------
// Single fused persistent kernel. Grid 296 x 256 threads, 2 CTAs/SM.
// Each CTA: one-time per-CTA prep (stride detect, max|W|, two-digit s8
// quantization of W directly into SMEM in MMA fragment order, column sums),
// then a persistent loop over 64-row half-tiles (tau = 0..4095).
// ---------------------------------------------------------------------------
static __global__ void __launch_bounds__(256, 2)
bf_main(const uint32_t* __restrict__ xw, const float* __restrict__ W,
        float* __restrict__ out)
{
    extern __shared__ __align__(16) char sm[];
    char*      sA    = sm;
    char*      sB1   = sm + SB1_OFF;
    char*      sB2   = sm + SB2_OFF;
    uint32_t*  bw0   = (uint32_t*)(sm + BW0_OFF);
    uint32_t*  bw1   = (uint32_t*)(sm + BW1_OFF);
    float*     scorr = (float*)(sm + CORR_OFF);
    float*     red   = (float*)(sm + RED_OFF);

    const int t = threadIdx.x, lane = t & 31, wid = t >> 5;

    // ---- stride detection: int64 input has all-zero odd u32 words ----
    int probe = 0;
    if (t < 128) probe = (int)xw[2 * t + 1];
    const int stride = __syncthreads_or(probe) ? 1 : 2;

    // ---- max|W| (float4 loads; 496*64 floats = 7936 float4) ----
    float mx = 0.f;
    const float4* W4 = (const float4*)W;
    for (int i = t; i < 7936; i += 256) {
        float4 v = W4[i];
        mx = fmaxf(mx, fmaxf(fmaxf(fabsf(v.x), fabsf(v.y)),
                             fmaxf(fabsf(v.z), fabsf(v.w))));
    }
    red[t] = mx;
    __syncthreads();
    for (int d = 128; d; d >>= 1) {
        if (t < d) red[t] = fmaxf(red[t], red[t + d]);
        __syncthreads();
    }
    const float maxabs = fmaxf(red[0], 1e-30f);
    __syncthreads();

    const float s1   = maxabs * (1.0f / 127.0f);
    const float inv1 = 127.0f / maxabs;
    const float inv2 = 128.0f / s1;
    const float sc   = (2.0f / 255.0f) * s1 * (1.0f / 128.0f);

    // ---- quantize W -> two s8 digits in fragment order; column sums ----
    {
        const int o = t & 63, slice = t >> 6;       // 4 k-slices per column
        float cs = 0.f;
        for (int i = 0; i < 128; i++) {
            int k = slice + 4 * i;                  // covers k = 0..511
            float w = (k < 496) ? W[k * 64 + o] : 0.f;
            cs += w;
            int d1 = __float2int_rn(w * inv1);
            d1 = max(-127, min(127, d1));
            float rr = w - s1 * (float)d1;
            int d2 = __float2int_rn(rr * inv2);     // in [-64, 64]
            int ks = k >> 5, wrd = (k >> 2) & 7;
            int tg = wrd & 3, hf = wrd >> 2, by = k & 3;
            int addr = o * COLB + ks * 32 + tg * 8 + hf * 4 + by;
            sB1[addr] = (signed char)d1;
            sB2[addr] = (signed char)d2;
        }
        red[slice * 64 + o] = cs;
    }
    __syncthreads();
    if (t < 64)
        scorr[t] = (red[t] + red[64 + t] + red[128 + t] + red[192 + t]) * (1.0f / 255.0f);
    if (t < 8) { bw0[128 + t] = 0u; bw1[128 + t] = 0u; }

    // ---- per-thread invariants: A build (row rl = t>>2, quarter q = t&3) ----
    const int rl = t >> 2, q = t & 3;
    const int s = rl & 7;
    const int gmod4 = (rl >> 3) & 3;
    const int g4b = rl >> 5;                         // 0..1; + 2*half at runtime
    const uint32_t sel0 = 0x3210u + 0x1111u * (uint32_t)gmod4;
    const uint32_t sel1 = sel0 + 0x1111u;
    const uint32_t M1 = 0x01010101u * ((0xFFu << s) & 0xFFu);
    const uint32_t M2 = 0x01010101u * (0xFFu >> (8 - s));
    char* rowp = sA + rl * COLA + q * 128;

    // ---- per-thread invariants: MMA (warp = 16-row m-block x 32-col n-half) ----
    const int mb = wid >> 1, nh = wid & 1;
    const int rb = mb * 16;
    const int gid = lane >> 2, tig = lane & 3;
    const int aOff = (rb + gid) * COLA + 4 * tig;
    const int colbase = nh * 32;
    const int bCol = (colbase + gid) * COLB + tig * 8;
    const int row0 = rb + gid;

    // ---- prologue bytes: tiles t0, t0+296 into bw0/bw1; t0+592 in regs ----
    const int t0 = blockIdx.x;
    {
        int nA = t0 >> 1;
        unsigned char* b0 = (unsigned char*)bw0;
        b0[t]       = (unsigned char)xw[((size_t)nA * 512 + t) * (size_t)stride];
        b0[t + 256] = (unsigned char)xw[((size_t)nA * 512 + t + 256) * (size_t)stride];
        int tB = t0 + 296; if (tB > 4095) tB = 4095;
        int nB = tB >> 1;
        unsigned char* b1 = (unsigned char*)bw1;
        b1[t]       = (unsigned char)xw[((size_t)nB * 512 + t) * (size_t)stride];
        b1[t + 256] = (unsigned char)xw[((size_t)nB * 512 + t + 256) * (size_t)stride];
    }
    uint32_t br0, br1;
    {
        int tC = t0 + 592; if (tC > 4095) tC = 4095;
        int nC = tC >> 1;
        br0 = xw[((size_t)nC * 512 + t) * (size_t)stride];
        br1 = xw[((size_t)nC * 512 + t + 256) * (size_t)stride];
    }
    __syncthreads();

    float corr0[4], corr1[4];
    #pragma unroll
    for (int nt = 0; nt < 4; nt++) {
        int col = colbase + nt * 8 + 2 * tig;
        corr0[nt] = scorr[col];
        corr1[nt] = scorr[col + 1];
    }

    int p = 0;
    for (int tau = t0; tau < 4096; tau += 296, p ^= 1) {
        const int n = tau >> 1, half = tau & 1;
        const int g4 = half * 2 + g4b;
        uint32_t* bwP = p ? bw1 : bw0;

        // ---- build A (64 rows x 512 centered window bytes) ----
        #pragma unroll
        for (int m = 0; m < 8; m++) {
            int wbase = q * 32 + m * 4;
            uint32_t A0 = bwP[wbase + g4];
            uint32_t acc[4];
            #pragma unroll
            for (int j = 0; j < 4; j++) {
                uint32_t B0 = bwP[wbase + g4 + j + 1];
                uint32_t X = __byte_perm(A0, B0, sel0);
                uint32_t Y = __byte_perm(A0, B0, sel1);
                acc[j] = (((X << s) & M1) | ((Y >> (8 - s)) & M2)) ^ 0x80808080u;
                A0 = B0;
            }
            *(uint4*)(rowp + m * 16) = make_uint4(acc[0], acc[1], acc[2], acc[3]);
        }
        __syncthreads();

        // ---- MMA over both digits ----
        int c1[16], c2[16];
        #pragma unroll
        for (int i = 0; i < 16; i++) { c1[i] = 0; c2[i] = 0; }

        const char* aR = sA + aOff;
        #pragma unroll
        for (int ks = 0; ks < 16; ks++) {
            int k0 = ks * 32;
            uint32_t a0 = *(const uint32_t*)(aR + k0);
            uint32_t a2 = *(const uint32_t*)(aR + k0 + 16);
            uint32_t a1 = *(const uint32_t*)(aR + 8 * COLA + k0);
            uint32_t a3 = *(const uint32_t*)(aR + 8 * COLA + k0 + 16);
            #pragma unroll
            for (int nt = 0; nt < 4; nt++) {
                uint2 b = *(const uint2*)(sB1 + bCol + nt * (8 * COLB) + k0);
                imma(c1 + 4 * nt, a0, a1, a2, a3, b.x, b.y);
                uint2 e = *(const uint2*)(sB2 + bCol + nt * (8 * COLB) + k0);
                imma(c2 + 4 * nt, a0, a1, a2, a3, e.x, e.y);
            }
        }

        // ---- epilogue: out = sc * ((C1<<7) + C2) + corr ----
        {
            float* po = out + (size_t)n * 8192 + (size_t)(half * 64 + row0) * 64;
            #pragma unroll
            for (int nt = 0; nt < 4; nt++) {
                int col = colbase + nt * 8 + 2 * tig;
                float2 v0, v1;
                v0.x = fmaf(sc, (float)((c1[4*nt+0] << 7) + c2[4*nt+0]), corr0[nt]);
                v0.y = fmaf(sc, (float)((c1[4*nt+1] << 7) + c2[4*nt+1]), corr1[nt]);
                v1.x = fmaf(sc, (float)((c1[4*nt+2] << 7) + c2[4*nt+2]), corr0[nt]);
                v1.y = fmaf(sc, (float)((c1[4*nt+3] << 7) + c2[4*nt+3]), corr1[nt]);
                __stcs((float2*)(po + col), v0);
                __stcs((float2*)(po + 8 * 64 + col), v1);
            }
        }

        // ---- recycle byte buffer: commit regs (tile tau+592), fetch tau+888 ----
        ((unsigned char*)bwP)[t]       = (unsigned char)br0;
        ((unsigned char*)bwP)[t + 256] = (unsigned char)br1;
        {
            int tN = tau + 888; if (tN > 4095) tN = 4095;
            int nN = tN >> 1;
            br0 = xw[((size_t)nN * 512 + t) * (size_t)stride];
            br1 = xw[((size_t)nN * 512 + t + 256) * (size_t)stride];
        }
        __syncthreads();
    }
}

// ---------------------------------------------------------------------------
extern "C" void kernel_launch(void* const* d_in, const int* in_sizes, int n_in,
                              void* d_out, int out_size)
{
    const uint32_t* xw  = (const uint32_t*)d_in[0];
    const float*    W   = (const float*)d_in[1];
    float*          out = (float*)d_out;

    cudaFuncSetAttribute(bf_main, cudaFuncAttributeMaxDynamicSharedMemorySize, SMEM_DYN);
    bf_main<<<296, 256, SMEM_DYN>>>(xw, W, out);
}

// round 13
// speedup vs baseline: 1.2100x; 1.0660x over previous
#include <cuda_runtime.h>
#include <stdint.h>

#define COLA 528                 // A row stride (bytes)
#define COLB 544                 // B col stride (bytes)
#define ASZ (128 * COLA)         // 67584
#define BSZ (64 * COLB)          // 34816

// SMEM: sA0 | sA1 | B1 | B2 | bw0 | bw1 | corr
#define SB1_OFF  (2 * ASZ)               // 135168
#define SB2_OFF  (2 * ASZ + BSZ)         // 169984
#define BW0_OFF  (2 * ASZ + 2 * BSZ)     // 204800
#define BW1_OFF  (BW0_OFF + 544)         // 205344
#define CORR_OFF (BW1_OFF + 544)         // 205888
#define SMEM_DYN (CORR_OFF + 256)        // 206144

// ---------------------------------------------------------------------------
__device__ __forceinline__ void imma(int* c, uint32_t a0, uint32_t a1,
                                     uint32_t a2, uint32_t a3,
                                     uint32_t b0, uint32_t b1) {
    asm volatile(
        "mma.sync.aligned.m16n8k32.row.col.s32.s8.s8.s32 "
        "{%0,%1,%2,%3}, {%4,%5,%6,%7}, {%8,%9}, {%0,%1,%2,%3};"
        : "+r"(c[0]), "+r"(c[1]), "+r"(c[2]), "+r"(c[3])
        : "r"(a0), "r"(a1), "r"(a2), "r"(a3), "r"(b0), "r"(b1));
}
__device__ __forceinline__ void imma16(int* c, uint32_t a0, uint32_t a1,
                                       uint32_t b0) {
    asm volatile(
        "mma.sync.aligned.m16n8k16.row.col.s32.s8.s8.s32 "
        "{%0,%1,%2,%3}, {%4,%5}, {%6}, {%0,%1,%2,%3};"
        : "+r"(c[0]), "+r"(c[1]), "+r"(c[2]), "+r"(c[3])
        : "r"(a0), "r"(a1), "r"(b0));
}

// ---------------------------------------------------------------------------
__device__ __forceinline__ void buildA(const uint32_t* __restrict__ bw, char* rowp,
                                       int q, int g4, uint32_t sel0, uint32_t sel1,
                                       uint32_t M1, uint32_t M2, int s)
{
    #pragma unroll
    for (int m = 0; m < 8; m++) {
        int wbase = q * 32 + m * 4;
        uint32_t A0 = bw[wbase + g4];
        uint32_t acc[4];
        #pragma unroll
        for (int j = 0; j < 4; j++) {
            uint32_t B0 = bw[wbase + g4 + j + 1];
            uint32_t X = __byte_perm(A0, B0, sel0);
            uint32_t Y = __byte_perm(A0, B0, sel1);
            acc[j] = (((X << s) & M1) | ((Y >> (8 - s)) & M2)) ^ 0x80808080u;
            A0 = B0;
        }
        *(uint4*)(rowp + m * 16) = make_uint4(acc[0], acc[1], acc[2], acc[3]);
    }
}

// ---------------------------------------------------------------------------
// Single fused persistent kernel: grid 148 x 512 threads, 1 CTA/SM.
// Per-CTA one-time prep (stride detect, max|W|, two-digit s8 quantization of W
// straight into SMEM in fragment order, column sums), then the R6 pipelined
// tile loop (double-buffered A, early/late warp stagger, 1 barrier/tile).
// ---------------------------------------------------------------------------
static __global__ void __launch_bounds__(512, 1)
bf_main(const uint32_t* __restrict__ xw, const float* __restrict__ W,
        float* __restrict__ out)
{
    extern __shared__ __align__(16) char sm[];
    char* sA0 = sm;
    char* sA1 = sm + ASZ;
    char* sB1 = sm + SB1_OFF;
    char* sB2 = sm + SB2_OFF;
    uint32_t* bw0 = (uint32_t*)(sm + BW0_OFF);
    uint32_t* bw1 = (uint32_t*)(sm + BW1_OFF);
    float* scorr  = (float*)(sm + CORR_OFF);
    float* red    = (float*)sm;              // prologue scratch (aliases sA0)

    const int t = threadIdx.x, lane = t & 31, wid = t >> 5;

    // ---- stride detection: int64 input has all-zero odd u32 words ----
    int probe = 0;
    if (t < 256) probe = (int)xw[2 * t + 1];
    const int stride = __syncthreads_or(probe) ? 1 : 2;

    // ---- max|W| ----
    float mx = 0.f;
    const float4* W4 = (const float4*)W;
    for (int i = t; i < 7936; i += 512) {
        float4 v = W4[i];
        mx = fmaxf(mx, fmaxf(fmaxf(fabsf(v.x), fabsf(v.y)),
                             fmaxf(fabsf(v.z), fabsf(v.w))));
    }
    red[t] = mx;
    __syncthreads();
    for (int d = 256; d; d >>= 1) {
        if (t < d) red[t] = fmaxf(red[t], red[t + d]);
        __syncthreads();
    }
    const float maxabs = fmaxf(red[0], 1e-30f);
    __syncthreads();

    const float s1   = maxabs * (1.0f / 127.0f);
    const float inv1 = 127.0f / maxabs;
    const float inv2 = 128.0f / s1;
    const float sc   = (2.0f / 255.0f) * s1 * (1.0f / 128.0f);

    // ---- quantize W -> two s8 digits (fragment order) + column sums ----
    {
        const int o = t & 63, slice = t >> 6;      // 8 k-slices per column
        float cs = 0.f;
        for (int i = 0; i < 64; i++) {
            int k = slice + 8 * i;                 // covers 0..511
            float w = (k < 496) ? W[k * 64 + o] : 0.f;
            cs += w;
            int d1 = __float2int_rn(w * inv1);
            d1 = max(-127, min(127, d1));
            float rr = w - s1 * (float)d1;
            int d2 = __float2int_rn(rr * inv2);    // in [-64, 64]
            int ks = k >> 5, wrd = (k >> 2) & 7;
            int tg = wrd & 3, hf = wrd >> 2, by = k & 3;
            int addr = o * COLB + ks * 32 + tg * 8 + hf * 4 + by;
            sB1[addr] = (signed char)d1;
            sB2[addr] = (signed char)d2;
        }
        red[slice * 64 + o] = cs;
    }
    __syncthreads();
    if (t < 64) {
        float csum = 0.f;
        #pragma unroll
        for (int sl = 0; sl < 8; sl++) csum += red[sl * 64 + t];
        scorr[t] = csum * (1.0f / 255.0f);
    }
    if (t < 8) { bw0[128 + t] = 0u; bw1[128 + t] = 0u; }

    // ---- per-thread invariants: A build (row t>>2, quarter t&3) ----
    const int r = t >> 2, q = t & 3;
    const int g = r >> 3, s = r & 7;
    const int g4 = g >> 2, gr = g & 3;
    const uint32_t sel0 = 0x3210u + 0x1111u * (uint32_t)gr;
    const uint32_t sel1 = sel0 + 0x1111u;
    const uint32_t M1 = 0x01010101u * ((0xFFu << s) & 0xFFu);
    const uint32_t M2 = 0x01010101u * (0xFFu >> (8 - s));
    char* rowp0 = sA0 + r * COLA + q * 128;
    char* rowp1 = sA1 + r * COLA + q * 128;

    // ---- per-thread invariants: MMA (warp = 16-row m-block x 32-col n-half) ----
    const int mb = wid >> 1, nh = wid & 1;
    const int rb = mb * 16;
    const int gid = lane >> 2, tig = lane & 3;
    const int aOff = (rb + gid) * COLA + 4 * tig;
    const int colbase = nh * 32;
    const int bCol = (colbase + gid) * COLB + tig * 8;
    const int row0 = rb + gid;
    const bool early = ((wid >> 2) & 1) != 0;

    const int n0 = blockIdx.x;

    // ---- byte prologue: bw0 <- n0, bw1 <- n0+148, breg <- n0+296 ----
    {
        unsigned char* b0 = (unsigned char*)bw0;
        unsigned char* b1 = (unsigned char*)bw1;
        b0[t] = (unsigned char)xw[((size_t)n0 * 512 + t) * (size_t)stride];
        b1[t] = (unsigned char)xw[((size_t)(n0 + 148) * 512 + t) * (size_t)stride];
    }
    uint32_t breg;
    {
        int nb = n0 + 296; if (nb > 2047) nb = 2047;
        breg = xw[((size_t)nb * 512 + t) * (size_t)stride];
    }
    __syncthreads();

    float corr0[4], corr1[4];
    #pragma unroll
    for (int nt = 0; nt < 4; nt++) {
        int col = colbase + nt * 8 + 2 * tig;
        corr0[nt] = scorr[col];
        corr1[nt] = scorr[col + 1];
    }

    buildA(bw0, rowp0, q, g4, sel0, sel1, M1, M2, s);
    __syncthreads();

    int p = 0;
    for (int n = n0; n < 2048; n += 148, p ^= 1) {
        const char* sA      = p ? sA1 : sA0;
        char*       rowpN   = p ? rowp0 : rowp1;     // build target = other A buf
        const uint32_t* bwN = p ? bw0 : bw1;         // bytes of tile n+148
        uint32_t*   bwS     = p ? bw1 : bw0;         // recycled -> bytes n+296
        const bool  haveNext = (n + 148) < 2048;

        if (early && haveNext)
            buildA(bwN, rowpN, q, g4, sel0, sel1, M1, M2, s);

        // ---- MMA over both digits: 15 x k32 + 1 x k16 tail (K=496) ----
        int c1[16], c2[16];
        #pragma unroll
        for (int i = 0; i < 16; i++) { c1[i] = 0; c2[i] = 0; }

        const char* aR = sA + aOff;
        #pragma unroll
        for (int ks = 0; ks < 15; ks++) {
            int k0 = ks * 32;
            uint32_t a0 = *(const uint32_t*)(aR + k0);
            uint32_t a2 = *(const uint32_t*)(aR + k0 + 16);
            uint32_t a1 = *(const uint32_t*)(aR + 8 * COLA + k0);
            uint32_t a3 = *(const uint32_t*)(aR + 8 * COLA + k0 + 16);
            #pragma unroll
            for (int nt = 0; nt < 4; nt++) {
                uint2 b = *(const uint2*)(sB1 + bCol + nt * (8 * COLB) + k0);
                imma(c1 + 4 * nt, a0, a1, a2, a3, b.x, b.y);
                uint2 e = *(const uint2*)(sB2 + bCol + nt * (8 * COLB) + k0);
                imma(c2 + 4 * nt, a0, a1, a2, a3, e.x, e.y);
            }
        }
        {   // tail: k = 480..495
            uint32_t a0 = *(const uint32_t*)(aR + 480);
            uint32_t a1 = *(const uint32_t*)(aR + 8 * COLA + 480);
            #pragma unroll
            for (int nt = 0; nt < 4; nt++) {
                uint32_t b = *(const uint32_t*)(sB1 + bCol + nt * (8 * COLB) + 480);
                imma16(c1 + 4 * nt, a0, a1, b);
                uint32_t e = *(const uint32_t*)(sB2 + bCol + nt * (8 * COLB) + 480);
                imma16(c2 + 4 * nt, a0, a1, e);
            }
        }

        // ---- epilogue: out = sc * ((C1<<7) + C2) + corr ----
        {
            float* po = out + (size_t)n * 8192;
            #pragma unroll
            for (int nt = 0; nt < 4; nt++) {
                int col = colbase + nt * 8 + 2 * tig;
                float2 v0, v1;
                v0.x = fmaf(sc, (float)((c1[4*nt+0] << 7) + c2[4*nt+0]), corr0[nt]);
                v0.y = fmaf(sc, (float)((c1[4*nt+1] << 7) + c2[4*nt+1]), corr1[nt]);
                v1.x = fmaf(sc, (float)((c1[4*nt+2] << 7) + c2[4*nt+2]), corr0[nt]);
                v1.y = fmaf(sc, (float)((c1[4*nt+3] << 7) + c2[4*nt+3]), corr1[nt]);
                __stcs((float2*)(po + row0 * 64 + col), v0);
                __stcs((float2*)(po + (row0 + 8) * 64 + col), v1);
            }
        }

        if (!early && haveNext)
            buildA(bwN, rowpN, q, g4, sel0, sel1, M1, M2, s);

        // ---- byte pipeline: commit reg byte (n+296), fetch (n+444) ----
        ((unsigned char*)bwS)[t] = (unsigned char)breg;
        {
            int nb = n + 444; if (nb > 2047) nb = 2047;
            breg = xw[((size_t)nb * 512 + t) * (size_t)stride];
        }
        __syncthreads();
    }
}

// ---------------------------------------------------------------------------
extern "C" void kernel_launch(void* const* d_in, const int* in_sizes, int n_in,
                              void* d_out, int out_size)
{
    const uint32_t* xw  = (const uint32_t*)d_in[0];
    const float*    W   = (const float*)d_in[1];
    float*          out = (float*)d_out;

    cudaFuncSetAttribute(bf_main, cudaFuncAttributeMaxDynamicSharedMemorySize, SMEM_DYN);
    bf_main<<<148, 512, SMEM_DYN>>>(xw, W, out);
}

// round 14
// speedup vs baseline: 1.2219x; 1.0098x over previous
#include <cuda_runtime.h>
#include <stdint.h>

#define COLA 528                  // A row stride (bytes)
#define COLB 544                  // B col stride (bytes)
#define PASZ (16 * COLA)          // 8448: per-pair A slab (16 rows)
#define BSZ  (64 * COLB)          // 34816 per digit

// SMEM: 8 pair-A slabs | B1 | B2 | 8 pair byte-bufs | corr
#define SB1_OFF  (8 * PASZ)               // 67584
#define SB2_OFF  (SB1_OFF + BSZ)          // 102400
#define BB_OFF   (SB2_OFF + BSZ)          // 137216 (8 x 544)
#define CORR_OFF (BB_OFF + 8 * 544)       // 141568
#define SMEM_DYN (CORR_OFF + 256)         // 141824

// ---------------------------------------------------------------------------
__device__ __forceinline__ void imma(int* c, uint32_t a0, uint32_t a1,
                                     uint32_t a2, uint32_t a3,
                                     uint32_t b0, uint32_t b1) {
    asm volatile(
        "mma.sync.aligned.m16n8k32.row.col.s32.s8.s8.s32 "
        "{%0,%1,%2,%3}, {%4,%5,%6,%7}, {%8,%9}, {%0,%1,%2,%3};"
        : "+r"(c[0]), "+r"(c[1]), "+r"(c[2]), "+r"(c[3])
        : "r"(a0), "r"(a1), "r"(a2), "r"(a3), "r"(b0), "r"(b1));
}

__device__ __forceinline__ void barpair(int id) {
    asm volatile("bar.sync %0, 64;" :: "r"(id) : "memory");
}

// pack the low bytes of four u32 values into one u32
__device__ __forceinline__ uint32_t pack4(uint32_t x0, uint32_t x1,
                                          uint32_t x2, uint32_t x3) {
    return __byte_perm(__byte_perm(x0, x1, 0x0040),
                       __byte_perm(x2, x3, 0x0040), 0x5410);
}

// fetch 8 input bytes (elements bi..bi+7 of tile n) into two packed words
__device__ __forceinline__ void fetch8(const uint32_t* __restrict__ xw,
                                       int n, int bi, int stride,
                                       uint32_t& w0, uint32_t& w1) {
    const uint32_t* p = xw + ((size_t)n * 512 + bi) * (size_t)stride;
    uint32_t v[8];
    #pragma unroll
    for (int j = 0; j < 8; j++) v[j] = p[j * stride];
    w0 = pack4(v[0], v[1], v[2], v[3]);
    w1 = pack4(v[4], v[5], v[6], v[7]);
}

// build 16-row A slab section: thread handles row (tp>>2), quarter (tp&3)
__device__ __forceinline__ void buildA(const uint32_t* __restrict__ bw, char* rowp,
                                       int q, int g4, uint32_t sel0, uint32_t sel1,
                                       uint32_t M1, uint32_t M2, int s)
{
    #pragma unroll
    for (int m = 0; m < 8; m++) {
        int wbase = q * 32 + m * 4;
        uint32_t A0 = bw[wbase + g4];
        uint32_t acc[4];
        #pragma unroll
        for (int j = 0; j < 4; j++) {
            uint32_t B0 = bw[wbase + g4 + j + 1];
            uint32_t X = __byte_perm(A0, B0, sel0);
            uint32_t Y = __byte_perm(A0, B0, sel1);
            acc[j] = (((X << s) & M1) | ((Y >> (8 - s)) & M2)) ^ 0x80808080u;
            A0 = B0;
        }
        *(uint4*)(rowp + m * 16) = make_uint4(acc[0], acc[1], acc[2], acc[3]);
    }
}

// ---------------------------------------------------------------------------
// Fused persistent kernel: grid 148 x 512, 1 CTA/SM.
// Prologue (CTA-wide): stride detect, max|W|, two-digit s8 quantization of W
// into SMEM fragment order, column sums. Steady state: 8 independent
// warp-pairs, each with private A slab + byte buffer, synced only by a
// 64-thread named barrier (no CTA barriers in the loop).
// ---------------------------------------------------------------------------
static __global__ void __launch_bounds__(512, 1)
bf_main(const uint32_t* __restrict__ xw, const float* __restrict__ W,
        float* __restrict__ out)
{
    extern __shared__ __align__(16) char sm[];
    char*  sB1   = sm + SB1_OFF;
    char*  sB2   = sm + SB2_OFF;
    float* scorr = (float*)(sm + CORR_OFF);
    float* red   = (float*)sm;               // prologue scratch (aliases A slabs)

    const int t = threadIdx.x, lane = t & 31, wid = t >> 5;

    // ---- stride detection: int64 input has all-zero odd u32 words ----
    int probe = 0;
    if (t < 256) probe = (int)xw[2 * t + 1];
    const int stride = __syncthreads_or(probe) ? 1 : 2;

    // ---- max|W| ----
    float mx = 0.f;
    const float4* W4 = (const float4*)W;
    for (int i = t; i < 7936; i += 512) {
        float4 v = W4[i];
        mx = fmaxf(mx, fmaxf(fmaxf(fabsf(v.x), fabsf(v.y)),
                             fmaxf(fabsf(v.z), fabsf(v.w))));
    }
    red[t] = mx;
    __syncthreads();
    for (int d = 256; d; d >>= 1) {
        if (t < d) red[t] = fmaxf(red[t], red[t + d]);
        __syncthreads();
    }
    const float maxabs = fmaxf(red[0], 1e-30f);
    __syncthreads();

    const float s1   = maxabs * (1.0f / 127.0f);
    const float inv1 = 127.0f / maxabs;
    const float inv2 = 128.0f / s1;
    const float sc   = (2.0f / 255.0f) * s1 * (1.0f / 128.0f);

    // ---- quantize W -> two s8 digits (fragment order) + column sums ----
    {
        const int o = t & 63, slice = t >> 6;       // 8 k-slices per column
        float cs = 0.f;
        for (int i = 0; i < 64; i++) {
            int k = slice + 8 * i;                  // covers 0..511
            float w = (k < 496) ? W[k * 64 + o] : 0.f;
            cs += w;
            int d1 = __float2int_rn(w * inv1);
            d1 = max(-127, min(127, d1));
            float rr = w - s1 * (float)d1;
            int d2 = __float2int_rn(rr * inv2);     // in [-64, 64]
            int ks = k >> 5, wrd = (k >> 2) & 7;
            int tg = wrd & 3, hf = wrd >> 2, by = k & 3;
            int addr = o * COLB + ks * 32 + tg * 8 + hf * 4 + by;
            sB1[addr] = (signed char)d1;
            sB2[addr] = (signed char)d2;
        }
        red[slice * 64 + o] = cs;
    }
    __syncthreads();
    if (t < 64) {
        float csum = 0.f;
        #pragma unroll
        for (int sl = 0; sl < 8; sl++) csum += red[sl * 64 + t];
        scorr[t] = csum * (1.0f / 255.0f);
    }
    __syncthreads();                        // prep done; pairs decouple below

    // ---- pair identity ----
    const int pr = wid >> 1;                // pair 0..7 (= m-block)
    const int tp = ((wid & 1) << 5) | lane; // 0..63 within pair
    char*      pA  = sm + pr * PASZ;
    uint32_t*  bbw = (uint32_t*)(sm + BB_OFF + pr * 544);
    const int  barid = pr + 1;

    // ---- invariants: A build (pair-local: row tp>>2 of 16, quarter tp&3) ----
    const int rl = tp >> 2, q = tp & 3;
    const int r = pr * 16 + rl;             // global row 0..127
    const int g = r >> 3, s = r & 7;
    const int g4 = g >> 2, gr = g & 3;
    const uint32_t sel0 = 0x3210u + 0x1111u * (uint32_t)gr;
    const uint32_t sel1 = sel0 + 0x1111u;
    const uint32_t M1 = 0x01010101u * ((0xFFu << s) & 0xFFu);
    const uint32_t M2 = 0x01010101u * (0xFFu >> (8 - s));
    char* rowp = pA + rl * COLA + q * 128;

    // ---- invariants: MMA ----
    const int nh = wid & 1;
    const int gid = lane >> 2, tig = lane & 3;
    const char* aR = pA + gid * COLA + 4 * tig;
    const int colbase = nh * 32;
    const int bCol = (colbase + gid) * COLB + tig * 8;
    const int row0 = pr * 16 + gid;

    float corr0[4], corr1[4];
    #pragma unroll
    for (int nt = 0; nt < 4; nt++) {
        int col = colbase + nt * 8 + 2 * tig;
        corr0[nt] = scorr[col];
        corr1[nt] = scorr[col + 1];
    }

    const int n0 = blockIdx.x;
    const int bi = tp * 8;                  // this thread's 8 bytes

    // ---- pair prologue: bbw <- bytes(n0), bregs <- bytes(n0+148) ----
    {
        uint32_t w0, w1;
        fetch8(xw, n0, bi, stride, w0, w1);
        bbw[tp * 2]     = w0;
        bbw[tp * 2 + 1] = w1;
        if (tp < 8) bbw[128 + tp] = 0u;
    }
    uint32_t br0, br1;
    {
        int nb = n0 + 148; if (nb > 2047) nb = 2047;
        fetch8(xw, nb, bi, stride, br0, br1);
    }
    barpair(barid);

    for (int n = n0; n < 2048; n += 148) {
        // ---- build A(n) from pair byte buffer ----
        buildA(bbw, rowp, q, g4, sel0, sel1, M1, M2, s);
        barpair(barid);                      // A ready; bbw reads done

        // ---- recycle byte buffer: commit bytes(n+148), prefetch (n+296) ----
        bbw[tp * 2]     = br0;
        bbw[tp * 2 + 1] = br1;
        {
            int nb = n + 296; if (nb > 2047) nb = 2047;
            fetch8(xw, nb, bi, stride, br0, br1);
        }

        // ---- MMA over both digits: 16 x k32 (K=512, zero-padded) ----
        int c1[16], c2[16];
        #pragma unroll
        for (int i = 0; i < 16; i++) { c1[i] = 0; c2[i] = 0; }

        #pragma unroll
        for (int ks = 0; ks < 16; ks++) {
            int k0 = ks * 32;
            uint32_t a0 = *(const uint32_t*)(aR + k0);
            uint32_t a2 = *(const uint32_t*)(aR + k0 + 16);
            uint32_t a1 = *(const uint32_t*)(aR + 8 * COLA + k0);
            uint32_t a3 = *(const uint32_t*)(aR + 8 * COLA + k0 + 16);
            #pragma unroll
            for (int nt = 0; nt < 4; nt++) {
                uint2 b = *(const uint2*)(sB1 + bCol + nt * (8 * COLB) + k0);
                imma(c1 + 4 * nt, a0, a1, a2, a3, b.x, b.y);
                uint2 e = *(const uint2*)(sB2 + bCol + nt * (8 * COLB) + k0);
                imma(c2 + 4 * nt, a0, a1, a2, a3, e.x, e.y);
            }
        }

        // ---- epilogue: out = sc * ((C1<<7) + C2) + corr ----
        {
            float* po = out + (size_t)n * 8192;
            #pragma unroll
            for (int nt = 0; nt < 4; nt++) {
                int col = colbase + nt * 8 + 2 * tig;
                float2 v0, v1;
                v0.x = fmaf(sc, (float)((c1[4*nt+0] << 7) + c2[4*nt+0]), corr0[nt]);
                v0.y = fmaf(sc, (float)((c1[4*nt+1] << 7) + c2[4*nt+1]), corr1[nt]);
                v1.x = fmaf(sc, (float)((c1[4*nt+2] << 7) + c2[4*nt+2]), corr0[nt]);
                v1.y = fmaf(sc, (float)((c1[4*nt+3] << 7) + c2[4*nt+3]), corr1[nt]);
                __stcs((float2*)(po + row0 * 64 + col), v0);
                __stcs((float2*)(po + (row0 + 8) * 64 + col), v1);
            }
        }

        barpair(barid);    // partner's MMA/A-reads + bbw commits complete
    }
}

// ---------------------------------------------------------------------------
extern "C" void kernel_launch(void* const* d_in, const int* in_sizes, int n_in,
                              void* d_out, int out_size)
{
    const uint32_t* xw  = (const uint32_t*)d_in[0];
    const float*    W   = (const float*)d_in[1];
    float*          out = (float*)d_out;

    cudaFuncSetAttribute(bf_main, cudaFuncAttributeMaxDynamicSharedMemorySize, SMEM_DYN);
    bf_main<<<148, 512, SMEM_DYN>>>(xw, W, out);
}

// round 15
// speedup vs baseline: 1.2419x; 1.0164x over previous
#include <cuda_runtime.h>
#include <stdint.h>

#define COLA 528                 // A row stride (bytes)
#define COLB 544                 // B col stride (bytes)
#define ASZ (128 * COLA)         // 67584
#define BSZ (64 * COLB)          // 34816

// SMEM: sA0 | sA1 | B1 | B2 | bb0 | bb1 | corr
#define SB1_OFF  (2 * ASZ)               // 135168
#define SB2_OFF  (2 * ASZ + BSZ)         // 169984
#define BB0_OFF  (2 * ASZ + 2 * BSZ)     // 204800
#define BB1_OFF  (BB0_OFF + 544)         // 205344
#define CORR_OFF (BB1_OFF + 544)         // 205888
#define SMEM_DYN (CORR_OFF + 256)        // 206144

static __device__ __align__(16) signed char g_Wd1[BSZ];
static __device__ __align__(16) signed char g_Wd2[BSZ];
static __device__ float g_corr[64];
static __device__ float g_sc;
static __device__ int   g_stride;

// ---------------------------------------------------------------------------
__device__ __forceinline__ void imma(int* c, uint32_t a0, uint32_t a1,
                                     uint32_t a2, uint32_t a3,
                                     uint32_t b0, uint32_t b1) {
    asm volatile(
        "mma.sync.aligned.m16n8k32.row.col.s32.s8.s8.s32 "
        "{%0,%1,%2,%3}, {%4,%5,%6,%7}, {%8,%9}, {%0,%1,%2,%3};"
        : "+r"(c[0]), "+r"(c[1]), "+r"(c[2]), "+r"(c[3])
        : "r"(a0), "r"(a1), "r"(a2), "r"(a3), "r"(b0), "r"(b1));
}

#define BAR_SYNC512(id)   asm volatile("bar.sync %0, 512;"   :: "r"(id) : "memory")
#define BAR_ARRIVE512(id) asm volatile("bar.arrive %0, 512;" :: "r"(id) : "memory")
#define BAR_SUP()         asm volatile("bar.sync 5, 256;"    ::: "memory")

// ---------------------------------------------------------------------------
// Prep (separate launch, known-good from R6): two-digit s8 quantization of W
// in MMA fragment order + column sums + input-width detection.
// ---------------------------------------------------------------------------
static __global__ void bf_prep(const float* __restrict__ W,
                               const uint32_t* __restrict__ xw)
{
    __shared__ float red[512];
    int o = blockIdx.x, k = threadIdx.x;

    if (o == 0 && k == 0) {
        uint32_t acc = 0;
        for (int j = 1; j < 256; j += 2) acc |= xw[j];
        g_stride = (acc == 0u) ? 2 : 1;
    }

    float mx = 0.f;
    for (int i = k; i < 496 * 64; i += 512) mx = fmaxf(mx, fabsf(W[i]));
    red[k] = mx;
    __syncthreads();
    for (int d = 256; d; d >>= 1) {
        if (k < d) red[k] = fmaxf(red[k], red[k + d]);
        __syncthreads();
    }
    float maxabs = fmaxf(red[0], 1e-30f);
    __syncthreads();

    float s1 = maxabs * (1.0f / 127.0f), inv1 = 127.0f / maxabs;
    float inv2 = 128.0f / s1;

    float w = (k < 496) ? W[k * 64 + o] : 0.f;
    int d1 = __float2int_rn(w * inv1);
    d1 = max(-127, min(127, d1));
    float r = w - s1 * (float)d1;
    int d2 = __float2int_rn(r * inv2);          // in [-64, 64]

    int ks = k >> 5, wrd = (k >> 2) & 7, tig = wrd & 3, hf = wrd >> 2, by = k & 3;
    int addr = o * COLB + ks * 32 + tig * 8 + hf * 4 + by;
    g_Wd1[addr] = (signed char)d1;
    g_Wd2[addr] = (signed char)d2;

    red[k] = w;
    __syncthreads();
    for (int d = 256; d; d >>= 1) {
        if (k < d) red[k] += red[k + d];
        __syncthreads();
    }
    if (k == 0) {
        g_corr[o] = red[0] * (1.0f / 255.0f);
        if (o == 0) g_sc = (2.0f / 255.0f) * s1 * (1.0f / 128.0f);
    }
}

// ---------------------------------------------------------------------------
__device__ __forceinline__ void buildA(const uint32_t* __restrict__ bw, char* rowp,
                                       int q, int g4, uint32_t sel0, uint32_t sel1,
                                       uint32_t M1, uint32_t M2, int s)
{
    #pragma unroll
    for (int m = 0; m < 8; m++) {
        int wbase = q * 32 + m * 4;
        uint32_t A0 = bw[wbase + g4];
        uint32_t acc[4];
        #pragma unroll
        for (int j = 0; j < 4; j++) {
            uint32_t B0 = bw[wbase + g4 + j + 1];
            uint32_t X = __byte_perm(A0, B0, sel0);
            uint32_t Y = __byte_perm(A0, B0, sel1);
            acc[j] = (((X << s) & M1) | ((Y >> (8 - s)) & M2)) ^ 0x80808080u;
            A0 = B0;
        }
        *(uint4*)(rowp + m * 16) = make_uint4(acc[0], acc[1], acc[2], acc[3]);
    }
}

// fetch 2 input bytes (elements 2ts, 2ts+1 of tile n) packed into one reg
__device__ __forceinline__ uint32_t fetch2(const uint32_t* __restrict__ xw,
                                           int n, int ts, int stride) {
    const uint32_t* p = xw + ((size_t)n * 512 + 2 * ts) * (size_t)stride;
    return (p[0] & 255u) | ((p[stride] & 255u) << 8);
}

// ---------------------------------------------------------------------------
// Warp-specialized persistent kernel: grid 148 x 512, 1 CTA/SM.
// Warps 0-7: pure MMA consumers (16-row m-block x 64 cols each).
// Warps 8-15: producers (byte fetch + A build) on double-buffered A.
// Handshake: named barriers full[p]=1+p, free[p]=3+p (512), support bar 5 (256).
// ---------------------------------------------------------------------------
static __global__ void __launch_bounds__(512, 1)
bf_main(const uint32_t* __restrict__ xw, float* __restrict__ out)
{
    extern __shared__ __align__(16) char sm[];
    char* sA0 = sm;
    char* sA1 = sm + ASZ;
    char* sB1 = sm + SB1_OFF;
    char* sB2 = sm + SB2_OFF;
    uint32_t* bb0 = (uint32_t*)(sm + BB0_OFF);
    uint32_t* bb1 = (uint32_t*)(sm + BB1_OFF);
    float* scorr  = (float*)(sm + CORR_OFF);

    const int t = threadIdx.x, lane = t & 31, wid = t >> 5;
    const int stride = g_stride;
    const float sc = g_sc;
    const int n0 = blockIdx.x;

    // ---- prologue: copy B digits + corr, zero byte pads ----
    {
        const uint4* w1 = (const uint4*)g_Wd1;
        const uint4* w2 = (const uint4*)g_Wd2;
        uint4* p1 = (uint4*)sB1;
        uint4* p2 = (uint4*)sB2;
        for (int i = t; i < BSZ / 16; i += 512) { p1[i] = w1[i]; p2[i] = w2[i]; }
        if (t < 64) scorr[t] = g_corr[t];
        if (t < 8)  { bb0[128 + t] = 0u; bb1[128 + t] = 0u; }
    }
    __syncthreads();

    if (wid < 8) {
        // ================= MMA CONSUMER WARPS =================
        const int rb = wid * 16;
        const int gid = lane >> 2, tig = lane & 3;
        const int aOff = rb * COLA + gid * COLA + 4 * tig;
        const int row0 = rb + gid;
        int bCol[8];
        #pragma unroll
        for (int nt = 0; nt < 8; nt++) bCol[nt] = (nt * 8 + gid) * COLB + tig * 8;
        float corr0[8], corr1[8];
        #pragma unroll
        for (int nt = 0; nt < 8; nt++) {
            int col = nt * 8 + 2 * tig;
            corr0[nt] = scorr[col];
            corr1[nt] = scorr[col + 1];
        }

        int i = 0;
        for (int n = n0; n < 2048; n += 148, i++) {
            const int p = i & 1;
            BAR_SYNC512(1 + p);                       // wait full[p]
            const char* aR = (p ? sA1 : sA0) + aOff;

            int c1[32], c2[32];
            #pragma unroll
            for (int j = 0; j < 32; j++) { c1[j] = 0; c2[j] = 0; }

            #pragma unroll
            for (int ks = 0; ks < 16; ks++) {
                int k0 = ks * 32;
                uint32_t a0 = *(const uint32_t*)(aR + k0);
                uint32_t a2 = *(const uint32_t*)(aR + k0 + 16);
                uint32_t a1 = *(const uint32_t*)(aR + 8 * COLA + k0);
                uint32_t a3 = *(const uint32_t*)(aR + 8 * COLA + k0 + 16);
                #pragma unroll
                for (int nt = 0; nt < 8; nt++) {
                    uint2 b = *(const uint2*)(sB1 + bCol[nt] + k0);
                    imma(c1 + 4 * nt, a0, a1, a2, a3, b.x, b.y);
                    uint2 e = *(const uint2*)(sB2 + bCol[nt] + k0);
                    imma(c2 + 4 * nt, a0, a1, a2, a3, e.x, e.y);
                }
            }

            // epilogue: out = sc * ((C1<<7) + C2) + corr
            {
                float* po = out + (size_t)n * 8192;
                #pragma unroll
                for (int nt = 0; nt < 8; nt++) {
                    int col = nt * 8 + 2 * tig;
                    float2 v0, v1;
                    v0.x = fmaf(sc, (float)((c1[4*nt+0] << 7) + c2[4*nt+0]), corr0[nt]);
                    v0.y = fmaf(sc, (float)((c1[4*nt+1] << 7) + c2[4*nt+1]), corr1[nt]);
                    v1.x = fmaf(sc, (float)((c1[4*nt+2] << 7) + c2[4*nt+2]), corr0[nt]);
                    v1.y = fmaf(sc, (float)((c1[4*nt+3] << 7) + c2[4*nt+3]), corr1[nt]);
                    __stcs((float2*)(po + row0 * 64 + col), v0);
                    __stcs((float2*)(po + (row0 + 8) * 64 + col), v1);
                }
            }
            BAR_ARRIVE512(3 + p);                     // signal free[p]
        }
    } else {
        // ================= SUPPORT PRODUCER WARPS =================
        const int sw = wid - 8;
        const int ts = sw * 32 + lane;                // 0..255: bytes 2ts, 2ts+1

        // two build tasks per thread: (row, quarter) pairs
        int qv[2], g4v[2], sv[2], rowOff[2];
        uint32_t sel0v[2], sel1v[2], M1v[2], M2v[2];
        #pragma unroll
        for (int j = 0; j < 2; j++) {
            int task = lane + 32 * j;                 // 0..63
            int rl = task >> 2, q = task & 3;
            int r = sw * 16 + rl;
            int g = r >> 3, s = r & 7;
            qv[j] = q;
            g4v[j] = g >> 2;
            sv[j] = s;
            sel0v[j] = 0x3210u + 0x1111u * (uint32_t)(g & 3);
            sel1v[j] = sel0v[j] + 0x1111u;
            M1v[j] = 0x01010101u * ((0xFFu << s) & 0xFFu);
            M2v[j] = 0x01010101u * (0xFFu >> (8 - s));
            rowOff[j] = r * COLA + q * 128;
        }

        uint32_t breg = fetch2(xw, n0, ts, stride);   // bytes(n0)

        int i = 0;
        for (int n = n0; n < 2048; n += 148, i++) {
            const int p = i & 1;
            uint32_t* bb = p ? bb1 : bb0;

            ((unsigned short*)bb)[ts] = (unsigned short)breg;
            {
                int nb = n + 148; if (nb > 2047) nb = 2047;
                breg = fetch2(xw, nb, ts, stride);
            }
            BAR_SUP();                                 // bb[p] committed
            if (i >= 2) BAR_SYNC512(3 + p);            // wait free[p]

            char* base = p ? sA1 : sA0;
            buildA(bb, base + rowOff[0], qv[0], g4v[0], sel0v[0], sel1v[0],
                   M1v[0], M2v[0], sv[0]);
            buildA(bb, base + rowOff[1], qv[1], g4v[1], sel0v[1], sel1v[1],
                   M1v[1], M2v[1], sv[1]);
            BAR_ARRIVE512(1 + p);                      // signal full[p]
        }
    }
}

// ---------------------------------------------------------------------------
extern "C" void kernel_launch(void* const* d_in, const int* in_sizes, int n_in,
                              void* d_out, int out_size)
{
    const uint32_t* xw  = (const uint32_t*)d_in[0];
    const float*    W   = (const float*)d_in[1];
    float*          out = (float*)d_out;

    cudaFuncSetAttribute(bf_main, cudaFuncAttributeMaxDynamicSharedMemorySize, SMEM_DYN);
    bf_prep<<<64, 512>>>(W, xw);
    bf_main<<<148, 512, SMEM_DYN>>>(xw, out);
}